// round 1
// baseline (speedup 1.0000x reference)
#include <cuda_runtime.h>
#include <math.h>

// ---------------- static scratch (no allocations allowed) ----------------
#define NMAX 50000
#define EMAX 500000

__device__ float  g_t [(size_t)256 * EMAX];   // 512 MB: layernorm-input scratch (edge & node & opens)
__device__ float  g_xn[(size_t)128 * NMAX];   // node features
__device__ float  g_si[(size_t)128 * NMAX];   // scatter i
__device__ float  g_sj[(size_t)128 * NMAX];   // scatter j
__device__ float  g_wEa[4 * 256 * 128];       // KE1[:, :128] + KE1[:,128:256]
__device__ float  g_wEb[4 * 256 * 128];       // KE1[:,256:384]
__device__ float  g_wNi[4 * 256 * 128];       // 0.5*KN1a + KN1b
__device__ float  g_wNj[4 * 256 * 128];       // 0.5*KN1a - KN1b
__device__ float  g_wNn[4 * 256 * 128];       // KN1c
__device__ double g_acc[20];                  // 10 layernorm instances x (sum, sumsq)

// ---------------- weight prep: fold concats into combined weights ----------------
__global__ void prep_kernel(const float* __restrict__ KE1, const float* __restrict__ KN1)
{
    int i = blockIdx.x * blockDim.x + threadIdx.x;
    if (i >= 4 * 256 * 128) return;
    int k = i & 127;
    int o = (i >> 7) & 255;
    int l = i >> 15;
    size_t base = ((size_t)l * 256 + o) * 384;
    const float* e = KE1 + base;
    const float* n = KN1 + base;
    int dst = (l << 15) + o * 128 + k;          // l*32768 + o*128 + k
    g_wEa[dst] = e[k] + e[128 + k];
    g_wEb[dst] = e[256 + k];
    float a = n[k], b = n[128 + k];
    g_wNi[dst] = 0.5f * a + b;
    g_wNj[dst] = 0.5f * a - b;
    g_wNn[dst] = n[256 + k];
}

// ---------------- fused matmul kernel ----------------
// Y[O, M] = sum_p W_p[O,K_p] @ X_p[K_p, M]
//  - pair0 may gather columns of X via g0 (edge mm1)
//  - optional input transform: relu((x - mean)*inv) from normAcc (consumer of layernorm)
//  - optional output stats accumulation (producer of layernorm)
//  - epi: 0 -> Y = acc ; 1 -> Y += 0.1*acc ; 2 -> Y += 0.1*acc AND atomic scatter acc to si/sj
// Tile: 64 columns x O rows per block, 256 threads, each thread owns (O/16) x 4 outputs.
template<int O>
__global__ void __launch_bounds__(256)
mm_kernel(int M,
          const float* __restrict__ W0, const float* __restrict__ X0, int K0, int ld0, const int* __restrict__ g0,
          const float* __restrict__ W1, const float* __restrict__ X1, int K1, int ld1,
          const float* __restrict__ W2, const float* __restrict__ X2, int K2, int ld2,
          const double* __restrict__ normAcc, double cntInv,
          double* __restrict__ statAcc,
          float* __restrict__ Y, int epi,
          float* __restrict__ si, float* __restrict__ sj,
          const int* __restrict__ iI, const int* __restrict__ jI, int Nn)
{
    constexpr int O16 = O / 16;
    __shared__ float Xs[32][64];
    __shared__ float Ws[O][32];
    __shared__ int   gidx[64];
    __shared__ int   idxI[64], idxJ[64];
    __shared__ float redS[256], redQ[256];

    int tid = threadIdx.x;
    int tx = tid & 15, ty = tid >> 4;
    int m0 = blockIdx.x * 64;

    float mean = 0.f, inv = 0.f;
    bool donorm = (normAcc != nullptr);
    if (donorm) {
        double mu  = normAcc[0] * cntInv;
        double var = normAcc[1] * cntInv - mu * mu;
        mean = (float)mu;
        inv  = (float)rsqrt(var + 1e-5);
    }

    if (g0)
        for (int i = tid; i < 64; i += 256) { int m = m0 + i; gidx[i] = (m < M) ? g0[m] : 0; }
    if (epi == 2)
        for (int i = tid; i < 64; i += 256) {
            int m = m0 + i;
            idxI[i] = (m < M) ? iI[m] : 0;
            idxJ[i] = (m < M) ? jI[m] : 0;
        }

    float acc[O16][4];
    #pragma unroll
    for (int r = 0; r < O16; r++) { acc[r][0] = acc[r][1] = acc[r][2] = acc[r][3] = 0.f; }

    const float* Wp[3] = {W0, W1, W2};
    const float* Xp[3] = {X0, X1, X2};
    int Kp[3] = {K0, K1, K2};
    int Lp[3] = {ld0, ld1, ld2};

    for (int p = 0; p < 3; p++) {
        const float* W = Wp[p];
        if (!W) break;
        const float* X = Xp[p];
        int K = Kp[p], ld = Lp[p];
        bool gath = (p == 0) && (g0 != nullptr);

        for (int k0 = 0; k0 < K; k0 += 32) {
            __syncthreads();
            // stage W tile: Ws[o][kk] = W[o][k0+kk]  (coalesced read, conflict-free write)
            #pragma unroll 4
            for (int i = tid; i < O * 32; i += 256) {
                int o = i >> 5, kk = i & 31;
                Ws[o][kk] = W[(size_t)o * K + k0 + kk];
            }
            // stage X tile
            if (gath) {
                #pragma unroll
                for (int i = tid; i < 32 * 64; i += 256) {
                    int kk = i >> 6, mm = i & 63;
                    float v = 0.f;
                    if (m0 + mm < M) v = X[(size_t)(k0 + kk) * ld + gidx[mm]];
                    Xs[kk][mm] = v;
                }
            } else {
                #pragma unroll
                for (int i = tid; i < 32 * 16; i += 256) {
                    int kk = i >> 4, m4 = (i & 15) * 4;
                    int m = m0 + m4;
                    float4 v = make_float4(0.f, 0.f, 0.f, 0.f);
                    if (m < M) v = *(const float4*)(X + (size_t)(k0 + kk) * ld + m);
                    if (donorm) {
                        v.x = fmaxf((v.x - mean) * inv, 0.f);
                        v.y = fmaxf((v.y - mean) * inv, 0.f);
                        v.z = fmaxf((v.z - mean) * inv, 0.f);
                        v.w = fmaxf((v.w - mean) * inv, 0.f);
                    }
                    *(float4*)&Xs[kk][m4] = v;
                }
            }
            __syncthreads();
            // compute: 32 k-steps
            for (int kq = 0; kq < 8; kq++) {
                float xr[4][4];
                #pragma unroll
                for (int q = 0; q < 4; q++) {
                    float4 t4 = *(const float4*)&Xs[kq * 4 + q][tx * 4];
                    xr[q][0] = t4.x; xr[q][1] = t4.y; xr[q][2] = t4.z; xr[q][3] = t4.w;
                }
                #pragma unroll
                for (int r = 0; r < O16; r++) {
                    float4 w4 = *(const float4*)&Ws[ty * O16 + r][kq * 4];
                    float wr[4] = {w4.x, w4.y, w4.z, w4.w};
                    #pragma unroll
                    for (int q = 0; q < 4; q++)
                        #pragma unroll
                        for (int c = 0; c < 4; c++)
                            acc[r][c] = fmaf(wr[q], xr[q][c], acc[r][c]);
                }
            }
        }
    }

    // output stats (producer side of global layernorm)
    if (statAcc) {
        float s = 0.f, q = 0.f;
        #pragma unroll
        for (int r = 0; r < O16; r++)
            #pragma unroll
            for (int c = 0; c < 4; c++) {
                if (m0 + tx * 4 + c < M) { float v = acc[r][c]; s += v; q += v * v; }
            }
        redS[tid] = s; redQ[tid] = q;
        __syncthreads();
        for (int st = 128; st > 0; st >>= 1) {
            if (tid < st) { redS[tid] += redS[tid + st]; redQ[tid] += redQ[tid + st]; }
            __syncthreads();
        }
        if (tid == 0) {
            atomicAdd(statAcc,     (double)redS[0]);
            atomicAdd(statAcc + 1, (double)redQ[0]);
        }
    }

    // epilogue (M is a multiple of 4, m0 multiple of 64 -> 4-col groups fully in/out)
    int mb = m0 + tx * 4;
    if (mb >= M) return;
    #pragma unroll
    for (int r = 0; r < O16; r++) {
        int o = ty * O16 + r;
        size_t off = (size_t)o * M + mb;
        if (epi == 0) {
            *(float4*)(Y + off) = make_float4(acc[r][0], acc[r][1], acc[r][2], acc[r][3]);
        } else if (epi == 1) {
            float4 old = *(float4*)(Y + off);
            old.x += 0.1f * acc[r][0]; old.y += 0.1f * acc[r][1];
            old.z += 0.1f * acc[r][2]; old.w += 0.1f * acc[r][3];
            *(float4*)(Y + off) = old;
        } else {
            float4 old = *(float4*)(Y + off);
            old.x += 0.1f * acc[r][0]; old.y += 0.1f * acc[r][1];
            old.z += 0.1f * acc[r][2]; old.w += 0.1f * acc[r][3];
            *(float4*)(Y + off) = old;
            #pragma unroll
            for (int c = 0; c < 4; c++) {
                float v = acc[r][c];
                atomicAdd(si + (size_t)o * Nn + idxI[tx * 4 + c], v);
                atomicAdd(sj + (size_t)o * Nn + idxJ[tx * 4 + c], v);
            }
        }
    }
}

// ---------------- host-side dispatch ----------------
static inline void mm_launch(int O, int M,
    const float* W0, const float* X0, int K0, int ld0, const int* g0,
    const float* W1, const float* X1, int K1, int ld1,
    const float* W2, const float* X2, int K2, int ld2,
    const double* nAcc, double cntInv, double* sAcc,
    float* Y, int epi, float* si, float* sj, const int* iI, const int* jI, int Nn)
{
    dim3 grid((M + 63) / 64);
    if (O == 256)
        mm_kernel<256><<<grid, 256>>>(M, W0, X0, K0, ld0, g0, W1, X1, K1, ld1, W2, X2, K2, ld2,
                                      nAcc, cntInv, sAcc, Y, epi, si, sj, iI, jI, Nn);
    else if (O == 128)
        mm_kernel<128><<<grid, 256>>>(M, W0, X0, K0, ld0, g0, W1, X1, K1, ld1, W2, X2, K2, ld2,
                                      nAcc, cntInv, sAcc, Y, epi, si, sj, iI, jI, Nn);
    else
        mm_kernel<64><<<grid, 256>>>(M, W0, X0, K0, ld0, g0, W1, X1, K1, ld1, W2, X2, K2, ld2,
                                     nAcc, cntInv, sAcc, Y, epi, si, sj, iI, jI, Nn);
}

extern "C" void kernel_launch(void* const* d_in, const int* in_sizes, int n_in,
                              void* d_out, int out_size)
{
    if (n_in < 13) return;
    const float* xn_in = (const float*)d_in[0];
    const float* xe_in = (const float*)d_in[1];
    const int*   iInd  = (const int*)d_in[2];
    const int*   jInd  = (const int*)d_in[3];
    const float* K1No  = (const float*)d_in[4];
    const float* K2No  = (const float*)d_in[5];
    const float* K1Eo  = (const float*)d_in[6];
    const float* K2Eo  = (const float*)d_in[7];
    const float* KNout = (const float*)d_in[8];
    const float* KE1   = (const float*)d_in[9];
    const float* KE2   = (const float*)d_in[10];
    const float* KN1   = (const float*)d_in[11];
    const float* KN2   = (const float*)d_in[12];

    int N = in_sizes[0] / 32;
    int E = in_sizes[1] / 32;

    float *t, *xn, *si, *sj, *wEa, *wEb, *wNi, *wNj, *wNn;
    double* acc;
    cudaGetSymbolAddress((void**)&t,   g_t);
    cudaGetSymbolAddress((void**)&xn,  g_xn);
    cudaGetSymbolAddress((void**)&si,  g_si);
    cudaGetSymbolAddress((void**)&sj,  g_sj);
    cudaGetSymbolAddress((void**)&wEa, g_wEa);
    cudaGetSymbolAddress((void**)&wEb, g_wEb);
    cudaGetSymbolAddress((void**)&wNi, g_wNi);
    cudaGetSymbolAddress((void**)&wNj, g_wNj);
    cudaGetSymbolAddress((void**)&wNn, g_wNn);
    cudaGetSymbolAddress((void**)&acc, g_acc);

    float* out = (float*)d_out;
    float* xe  = out + (size_t)64 * N;   // xe lives in the output buffer, updated in place

    cudaMemsetAsync(acc, 0, 20 * sizeof(double), 0);
    prep_kernel<<<(4 * 256 * 128 + 255) / 256, 256>>>(KE1, KN1);

    const float* NUL = nullptr;

    // opening: xn = double_layer(xn, K1Nopen, K2Nopen)    [slot 0]
    mm_launch(128, N, K1No, xn_in, 32, N, nullptr, NUL,0,0,0, NUL,0,0,0,
              nullptr, 0.0, acc + 0, t, 0, nullptr, nullptr, nullptr, nullptr, 0);
    mm_launch(128, N, K2No, t, 128, N, nullptr, NUL,0,0,0, NUL,0,0,0,
              acc + 0, 1.0 / (128.0 * N), nullptr, xn, 0, nullptr, nullptr, nullptr, nullptr, 0);

    // opening: xe = double_layer(xe, K1Eopen, K2Eopen)    [slot 1]
    mm_launch(128, E, K1Eo, xe_in, 32, E, nullptr, NUL,0,0,0, NUL,0,0,0,
              nullptr, 0.0, acc + 2, t, 0, nullptr, nullptr, nullptr, nullptr, 0);
    mm_launch(128, E, K2Eo, t, 128, E, nullptr, NUL,0,0,0, NUL,0,0,0,
              acc + 2, 1.0 / (128.0 * E), nullptr, xe, 0, nullptr, nullptr, nullptr, nullptr, 0);

    for (int l = 0; l < 4; l++) {
        double* accE = acc + 4 + 4 * l;   // edge layernorm slot
        double* accN = acc + 6 + 4 * l;   // node layernorm slot
        size_t ws = (size_t)l * 32768;    // 256*128 per layer (also 128*256 for KE2/KN2)

        // edge mm1: t[256,E] = wEa @ xn[:, iInd]  +  wEb @ xe   (+ stats)
        mm_launch(256, E, wEa + ws, xn, 128, N, iInd,
                  wEb + ws, xe, 128, E, NUL, 0, 0, 0,
                  nullptr, 0.0, accE, t, 0, nullptr, nullptr, nullptr, nullptr, 0);

        cudaMemsetAsync(si, 0, (size_t)128 * N * sizeof(float), 0);
        cudaMemsetAsync(sj, 0, (size_t)128 * N * sizeof(float), 0);

        // edge mm2: xec = KE2 @ relu(norm(t)); xe += 0.1*xec; scatter xec -> si, sj
        mm_launch(128, E, KE2 + ws, t, 256, E, nullptr, NUL,0,0,0, NUL,0,0,0,
                  accE, 1.0 / (256.0 * E), nullptr, xe, 2, si, sj, iInd, jInd, N);

        // node mm1: u[256,N] = Wi@si + Wj@sj + Wn@xn   (+ stats)
        mm_launch(256, N, wNi + ws, si, 128, N, nullptr,
                  wNj + ws, sj, 128, N,
                  wNn + ws, xn, 128, N,
                  nullptr, 0.0, accN, t, 0, nullptr, nullptr, nullptr, nullptr, 0);

        // node mm2: xn += 0.1 * (KN2 @ relu(norm(u)))
        mm_launch(128, N, KN2 + ws, t, 256, N, nullptr, NUL,0,0,0, NUL,0,0,0,
                  accN, 1.0 / (256.0 * N), nullptr, xn, 1, nullptr, nullptr, nullptr, nullptr, 0);
    }

    // final: out_xn[64,N] = KNout @ xn
    mm_launch(64, N, KNout, xn, 128, N, nullptr, NUL,0,0,0, NUL,0,0,0,
              nullptr, 0.0, nullptr, out, 0, nullptr, nullptr, nullptr, nullptr, 0);
}

// round 2
// speedup vs baseline: 1.8411x; 1.8411x over previous
#include <cuda_runtime.h>
#include <math.h>

#define NMAX 50000
#define EMAX 500000

// ---------------- static scratch ----------------
__device__ float  g_t [(size_t)256 * EMAX];
__device__ float  g_xn[(size_t)128 * NMAX];
__device__ float  g_si[(size_t)128 * NMAX];
__device__ float  g_sj[(size_t)128 * NMAX];
// transposed (k-major) weights
__device__ float  g_wEa[4 * 128 * 256];   // [l][k][o]  (KE1a+KE1b)
__device__ float  g_wEb[4 * 128 * 256];   // KE1c
__device__ float  g_wNi[4 * 128 * 256];   // 0.5*KN1a + KN1b
__device__ float  g_wNj[4 * 128 * 256];   // 0.5*KN1a - KN1b
__device__ float  g_wNn[4 * 128 * 256];   // KN1c
__device__ float  g_wE2[4 * 256 * 128];   // KE2^T
__device__ float  g_wN2[4 * 256 * 128];   // KN2^T
__device__ float  g_k1n[32 * 128];
__device__ float  g_k2n[128 * 128];
__device__ float  g_k1e[32 * 128];
__device__ float  g_k2e[128 * 128];
__device__ float  g_ko [128 * 128];       // KNout^T zero-padded to 128 rows-out
__device__ double g_acc[20];

// ---------------- f32x2 helpers ----------------
__device__ __forceinline__ unsigned long long dup2(float v) {
    unsigned long long r;
    asm("mov.b64 %0, {%1, %1};" : "=l"(r) : "f"(v));
    return r;
}
__device__ __forceinline__ void ffma2(unsigned long long& d, unsigned long long a, unsigned long long b) {
    asm("fma.rn.f32x2 %0, %1, %2, %0;" : "+l"(d) : "l"(a), "l"(b));
}
__device__ __forceinline__ float2 f2of(unsigned long long u) {
    union { unsigned long long u; float2 f; } cv; cv.u = u; return cv.f;
}

// ---------------- weight prep: fold concats + transpose to k-major ----------------
__global__ void prep_kernelA(const float* __restrict__ KE1, const float* __restrict__ KN1,
                             const float* __restrict__ KE2, const float* __restrict__ KN2)
{
    int idx = blockIdx.x * blockDim.x + threadIdx.x;
    if (idx >= 4 * 128 * 256) return;
    int l = idx >> 15;
    int r = idx & 32767;
    // part A: o in [0,256), k in [0,128): dst = l*32768 + k*256 + o
    {
        int o = r & 255, k = r >> 8;
        size_t src = ((size_t)l * 256 + o) * 384;
        int dst = (l << 15) + k * 256 + o;
        const float* e = KE1 + src;
        const float* n = KN1 + src;
        g_wEa[dst] = e[k] + e[128 + k];
        g_wEb[dst] = e[256 + k];
        float a = n[k], b = n[128 + k];
        g_wNi[dst] = 0.5f * a + b;
        g_wNj[dst] = 0.5f * a - b;
        g_wNn[dst] = n[256 + k];
    }
    // part B: KE2/KN2 transpose: o in [0,128), k in [0,256)
    {
        int o = r & 127, k = r >> 7;
        int dst = (l << 15) + k * 128 + o;
        g_wE2[dst] = KE2[((size_t)l * 128 + o) * 256 + k];
        g_wN2[dst] = KN2[((size_t)l * 128 + o) * 256 + k];
    }
}

__global__ void prep_kernelB(const float* __restrict__ K1No, const float* __restrict__ K2No,
                             const float* __restrict__ K1Eo, const float* __restrict__ K2Eo,
                             const float* __restrict__ KNout)
{
    int idx = blockIdx.x * blockDim.x + threadIdx.x;
    if (idx >= 128 * 128) return;
    int o = idx & 127, k = idx >> 7;
    if (k < 32) {
        g_k1n[k * 128 + o] = K1No[o * 32 + k];
        g_k1e[k * 128 + o] = K1Eo[o * 32 + k];
    }
    g_k2n[k * 128 + o] = K2No[o * 128 + k];
    g_k2e[k * 128 + o] = K2Eo[o * 128 + k];
    g_ko [k * 128 + o] = (o < 64) ? KNout[o * 128 + k] : 0.f;
}

// ---------------- fused f32x2 GEMM ----------------
// Y[wb+0..127, m0..m0+127] += / = sum_p W_p^T-slice @ X_p  with optional gather (pair0),
// optional layernorm+relu on X (single-pair consumers), optional global stats, optional scatter.
__global__ void __launch_bounds__(256, 2)
mm2_kernel(int M, int Oact, int Nn,
           const float* __restrict__ W0, const float* __restrict__ X0, int K0a, int ld0, int ldW0, const int* __restrict__ g0,
           const float* __restrict__ W1, const float* __restrict__ X1, int K1a, int ld1, int ldW1,
           const float* __restrict__ W2, const float* __restrict__ X2, int K2a, int ld2, int ldW2,
           const double* __restrict__ normAcc, double cntInv,
           double* __restrict__ statAcc,
           float* __restrict__ Y, int epi,
           float* __restrict__ si, float* __restrict__ sj,
           const int* __restrict__ iI, const int* __restrict__ jI)
{
    __shared__ __align__(16) float Ws[8][132];
    __shared__ __align__(16) float Xs[8][132];
    __shared__ int gidx[128], idxI[128], idxJ[128];

    const int tid  = threadIdx.x;
    const int m0   = blockIdx.x * 128;
    const int wb   = blockIdx.y * 128;
    const int lane = tid & 31;
    const int warp = tid >> 5;
    const int wrow = warp >> 2, wcol = warp & 3;
    const int col_t = lane & 3, row_t = lane >> 2;
    const int rbase = wrow * 64 + row_t * 4;
    const int cbase = wcol * 32 + col_t * 4;

    float mean = 0.f, inv = 0.f;
    const bool donorm = (normAcc != nullptr);
    if (donorm) {
        double mu = normAcc[0] * cntInv;
        double va = normAcc[1] * cntInv - mu * mu;
        mean = (float)mu;
        inv  = (float)rsqrt(va + 1e-5);
    }

    if (g0)
        for (int i = tid; i < 128; i += 256) { int m = m0 + i; gidx[i] = (m < M) ? g0[m] : 0; }
    if (epi == 2)
        for (int i = tid; i < 128; i += 256) {
            int m = m0 + i;
            idxI[i] = (m < M) ? iI[m] : 0;
            idxJ[i] = (m < M) ? jI[m] : 0;
        }
    __syncthreads();   // gidx/idx ready before any prefetch reads them

    unsigned long long acc[8][4];
    #pragma unroll
    for (int r = 0; r < 8; r++)
        #pragma unroll
        for (int c = 0; c < 4; c++) acc[r][c] = 0ull;

    const int Ks0 = K0a;
    const int Ks1 = W1 ? K1a : 0;
    const int Ks2 = W2 ? K2a : 0;
    const int totT = (Ks0 + Ks1 + Ks2) >> 3;

    float4 wpre, xpre;
    float xg0 = 0.f, xg1 = 0.f, xg2 = 0.f, xg3 = 0.f;
    int pcur = 0, kcur = 0;

    const int kkS = tid >> 5;          // staging row
    const int mfS = (tid & 31) * 4;    // staging col

    auto prefetch = [&](int p, int k0) {
        const float *W, *X; int ld, ldW; const int* gg = nullptr;
        if (p == 0)      { W = W0; X = X0; ld = ld0; ldW = ldW0; gg = g0; }
        else if (p == 1) { W = W1; X = X1; ld = ld1; ldW = ldW1; }
        else             { W = W2; X = X2; ld = ld2; ldW = ldW2; }
        wpre = *(const float4*)(W + (size_t)(k0 + kkS) * ldW + wb + mfS);
        if (gg) {
            int i0 = tid, i1 = tid + 256, i2 = tid + 512, i3 = tid + 768;
            xg0 = (m0 + (i0 & 127) < M) ? X[(size_t)(k0 + (i0 >> 7)) * ld + gidx[i0 & 127]] : 0.f;
            xg1 = (m0 + (i1 & 127) < M) ? X[(size_t)(k0 + (i1 >> 7)) * ld + gidx[i1 & 127]] : 0.f;
            xg2 = (m0 + (i2 & 127) < M) ? X[(size_t)(k0 + (i2 >> 7)) * ld + gidx[i2 & 127]] : 0.f;
            xg3 = (m0 + (i3 & 127) < M) ? X[(size_t)(k0 + (i3 >> 7)) * ld + gidx[i3 & 127]] : 0.f;
        } else {
            int m = m0 + mfS;
            if (m < M) {
                float4 v = *(const float4*)(X + (size_t)(k0 + kkS) * ld + m);
                if (donorm) {
                    v.x = fmaxf((v.x - mean) * inv, 0.f);
                    v.y = fmaxf((v.y - mean) * inv, 0.f);
                    v.z = fmaxf((v.z - mean) * inv, 0.f);
                    v.w = fmaxf((v.w - mean) * inv, 0.f);
                }
                xpre = v;
            } else xpre = make_float4(0.f, 0.f, 0.f, 0.f);
        }
    };

    prefetch(0, 0);

    for (int tt = 0; tt < totT; tt++) {
        __syncthreads();
        // commit prefetched tile to smem
        *(float4*)&Ws[kkS][mfS] = wpre;
        if (pcur == 0 && g0) {
            Xs[(tid)       >> 7][(tid)       & 127] = xg0;
            Xs[(tid + 256) >> 7][(tid + 256) & 127] = xg1;
            Xs[(tid + 512) >> 7][(tid + 512) & 127] = xg2;
            Xs[(tid + 768) >> 7][(tid + 768) & 127] = xg3;
        } else {
            *(float4*)&Xs[kkS][mfS] = xpre;
        }
        __syncthreads();

        // advance + prefetch next tile (overlaps with compute)
        int pn = pcur, kn = kcur + 8;
        if (pn == 0 && kn >= Ks0) { pn = 1; kn = 0; }
        if (pn == 1 && kn >= Ks1) { pn = 2; kn = 0; }
        if (pn == 2 && kn >= Ks2) { pn = 3; }
        if (pn < 3) prefetch(pn, kn);
        pcur = pn; kcur = kn;

        // compute 8 k-steps
        #pragma unroll
        for (int kk = 0; kk < 8; kk++) {
            float4 wa = *(const float4*)&Ws[kk][rbase];
            float4 wbv = *(const float4*)&Ws[kk][rbase + 32];
            ulonglong2 xa = *(const ulonglong2*)&Xs[kk][cbase];
            ulonglong2 xb = *(const ulonglong2*)&Xs[kk][cbase + 16];
            unsigned long long d;
            d = dup2(wa.x);  ffma2(acc[0][0], d, xa.x); ffma2(acc[0][1], d, xa.y); ffma2(acc[0][2], d, xb.x); ffma2(acc[0][3], d, xb.y);
            d = dup2(wa.y);  ffma2(acc[1][0], d, xa.x); ffma2(acc[1][1], d, xa.y); ffma2(acc[1][2], d, xb.x); ffma2(acc[1][3], d, xb.y);
            d = dup2(wa.z);  ffma2(acc[2][0], d, xa.x); ffma2(acc[2][1], d, xa.y); ffma2(acc[2][2], d, xb.x); ffma2(acc[2][3], d, xb.y);
            d = dup2(wa.w);  ffma2(acc[3][0], d, xa.x); ffma2(acc[3][1], d, xa.y); ffma2(acc[3][2], d, xb.x); ffma2(acc[3][3], d, xb.y);
            d = dup2(wbv.x); ffma2(acc[4][0], d, xa.x); ffma2(acc[4][1], d, xa.y); ffma2(acc[4][2], d, xb.x); ffma2(acc[4][3], d, xb.y);
            d = dup2(wbv.y); ffma2(acc[5][0], d, xa.x); ffma2(acc[5][1], d, xa.y); ffma2(acc[5][2], d, xb.x); ffma2(acc[5][3], d, xb.y);
            d = dup2(wbv.z); ffma2(acc[6][0], d, xa.x); ffma2(acc[6][1], d, xa.y); ffma2(acc[6][2], d, xb.x); ffma2(acc[6][3], d, xb.y);
            d = dup2(wbv.w); ffma2(acc[7][0], d, xa.x); ffma2(acc[7][1], d, xa.y); ffma2(acc[7][2], d, xb.x); ffma2(acc[7][3], d, xb.y);
        }
    }

    // ----- layernorm stats (producer) -----
    if (statAcc) {
        float s = 0.f, q = 0.f;
        #pragma unroll
        for (int r = 0; r < 8; r++)
            #pragma unroll
            for (int cg = 0; cg < 2; cg++) {
                if (m0 + cbase + cg * 16 < M) {
                    float2 v0 = f2of(acc[r][cg * 2 + 0]);
                    float2 v1 = f2of(acc[r][cg * 2 + 1]);
                    s += v0.x + v0.y + v1.x + v1.y;
                    q += v0.x * v0.x + v0.y * v0.y + v1.x * v1.x + v1.y * v1.y;
                }
            }
        __syncthreads();                 // done reading Ws/Xs; overlay reduction
        float* redS = (float*)Ws;        // 256 floats
        float* redQ = ((float*)Ws) + 256;
        redS[tid] = s; redQ[tid] = q;
        __syncthreads();
        for (int st = 128; st > 0; st >>= 1) {
            if (tid < st) { redS[tid] += redS[tid + st]; redQ[tid] += redQ[tid + st]; }
            __syncthreads();
        }
        if (tid == 0) {
            atomicAdd(statAcc,     (double)redS[0]);
            atomicAdd(statAcc + 1, (double)redQ[0]);
        }
    }

    // ----- epilogue -----
    #pragma unroll
    for (int r = 0; r < 8; r++) {
        int lrow = (r < 4) ? (rbase + r) : (rbase + 32 + r - 4);
        int o = wb + lrow;
        if (o >= Oact) continue;
        #pragma unroll
        for (int cg = 0; cg < 2; cg++) {
            int c = m0 + cbase + cg * 16;
            if (c >= M) continue;
            float2 p0 = f2of(acc[r][cg * 2 + 0]);
            float2 p1 = f2of(acc[r][cg * 2 + 1]);
            size_t off = (size_t)o * M + c;
            if (epi == 0) {
                *(float4*)(Y + off) = make_float4(p0.x, p0.y, p1.x, p1.y);
            } else {
                float4 old = *(float4*)(Y + off);
                old.x += 0.1f * p0.x; old.y += 0.1f * p0.y;
                old.z += 0.1f * p1.x; old.w += 0.1f * p1.y;
                *(float4*)(Y + off) = old;
                if (epi == 2) {
                    int lc = cbase + cg * 16;
                    atomicAdd(si + (size_t)o * Nn + idxI[lc + 0], p0.x);
                    atomicAdd(si + (size_t)o * Nn + idxI[lc + 1], p0.y);
                    atomicAdd(si + (size_t)o * Nn + idxI[lc + 2], p1.x);
                    atomicAdd(si + (size_t)o * Nn + idxI[lc + 3], p1.y);
                    atomicAdd(sj + (size_t)o * Nn + idxJ[lc + 0], p0.x);
                    atomicAdd(sj + (size_t)o * Nn + idxJ[lc + 1], p0.y);
                    atomicAdd(sj + (size_t)o * Nn + idxJ[lc + 2], p1.x);
                    atomicAdd(sj + (size_t)o * Nn + idxJ[lc + 3], p1.y);
                }
            }
        }
    }
}

// ---------------- host-side dispatch ----------------
static inline void mm_launch(int gridy, int M, int Oact,
    const float* W0, const float* X0, int K0, int ld0, int ldW0, const int* g0,
    const float* W1, const float* X1, int K1, int ld1, int ldW1,
    const float* W2, const float* X2, int K2, int ld2, int ldW2,
    const double* nAcc, double cntInv, double* sAcc,
    float* Y, int epi, float* si, float* sj, const int* iI, const int* jI, int Nn)
{
    dim3 grid((M + 127) / 128, gridy);
    mm2_kernel<<<grid, 256>>>(M, Oact, Nn,
        W0, X0, K0, ld0, ldW0, g0,
        W1, X1, K1, ld1, ldW1,
        W2, X2, K2, ld2, ldW2,
        nAcc, cntInv, sAcc, Y, epi, si, sj, iI, jI);
}

extern "C" void kernel_launch(void* const* d_in, const int* in_sizes, int n_in,
                              void* d_out, int out_size)
{
    if (n_in < 13) return;
    const float* xn_in = (const float*)d_in[0];
    const float* xe_in = (const float*)d_in[1];
    const int*   iInd  = (const int*)d_in[2];
    const int*   jInd  = (const int*)d_in[3];
    const float* K1No  = (const float*)d_in[4];
    const float* K2No  = (const float*)d_in[5];
    const float* K1Eo  = (const float*)d_in[6];
    const float* K2Eo  = (const float*)d_in[7];
    const float* KNout = (const float*)d_in[8];
    const float* KE1   = (const float*)d_in[9];
    const float* KE2   = (const float*)d_in[10];
    const float* KN1   = (const float*)d_in[11];
    const float* KN2   = (const float*)d_in[12];

    int N = in_sizes[0] / 32;
    int E = in_sizes[1] / 32;

    float *t, *xn, *si, *sj, *wEa, *wEb, *wNi, *wNj, *wNn, *wE2, *wN2;
    float *k1n, *k2n, *k1e, *k2e, *ko;
    double* acc;
    cudaGetSymbolAddress((void**)&t,   g_t);
    cudaGetSymbolAddress((void**)&xn,  g_xn);
    cudaGetSymbolAddress((void**)&si,  g_si);
    cudaGetSymbolAddress((void**)&sj,  g_sj);
    cudaGetSymbolAddress((void**)&wEa, g_wEa);
    cudaGetSymbolAddress((void**)&wEb, g_wEb);
    cudaGetSymbolAddress((void**)&wNi, g_wNi);
    cudaGetSymbolAddress((void**)&wNj, g_wNj);
    cudaGetSymbolAddress((void**)&wNn, g_wNn);
    cudaGetSymbolAddress((void**)&wE2, g_wE2);
    cudaGetSymbolAddress((void**)&wN2, g_wN2);
    cudaGetSymbolAddress((void**)&k1n, g_k1n);
    cudaGetSymbolAddress((void**)&k2n, g_k2n);
    cudaGetSymbolAddress((void**)&k1e, g_k1e);
    cudaGetSymbolAddress((void**)&k2e, g_k2e);
    cudaGetSymbolAddress((void**)&ko,  g_ko);
    cudaGetSymbolAddress((void**)&acc, g_acc);

    float* out = (float*)d_out;
    float* xe  = out + (size_t)64 * N;

    cudaMemsetAsync(acc, 0, 20 * sizeof(double), 0);
    prep_kernelA<<<(4 * 128 * 256 + 255) / 256, 256>>>(KE1, KN1, KE2, KN2);
    prep_kernelB<<<(128 * 128 + 255) / 256, 256>>>(K1No, K2No, K1Eo, K2Eo, KNout);

    const float* NUL = nullptr;

    // opening node: [slot 0]
    mm_launch(1, N, 128, k1n, xn_in, 32, N, 128, nullptr, NUL,0,0,0,0, NUL,0,0,0,0,
              nullptr, 0.0, acc + 0, t, 0, nullptr, nullptr, nullptr, nullptr, 0);
    mm_launch(1, N, 128, k2n, t, 128, N, 128, nullptr, NUL,0,0,0,0, NUL,0,0,0,0,
              acc + 0, 1.0 / (128.0 * N), nullptr, xn, 0, nullptr, nullptr, nullptr, nullptr, 0);

    // opening edge: [slot 1]
    mm_launch(1, E, 128, k1e, xe_in, 32, E, 128, nullptr, NUL,0,0,0,0, NUL,0,0,0,0,
              nullptr, 0.0, acc + 2, t, 0, nullptr, nullptr, nullptr, nullptr, 0);
    mm_launch(1, E, 128, k2e, t, 128, E, 128, nullptr, NUL,0,0,0,0, NUL,0,0,0,0,
              acc + 2, 1.0 / (128.0 * E), nullptr, xe, 0, nullptr, nullptr, nullptr, nullptr, 0);

    for (int l = 0; l < 4; l++) {
        double* accE = acc + 4 + 4 * l;
        double* accN = acc + 6 + 4 * l;
        size_t ws = (size_t)l * 32768;

        // edge mm1: t[256,E] = wEa @ xn[:,iInd] + wEb @ xe   (+stats)
        mm_launch(2, E, 256, wEa + ws, xn, 128, N, 256, iInd,
                  wEb + ws, xe, 128, E, 256,
                  NUL, 0, 0, 0, 0,
                  nullptr, 0.0, accE, t, 0, nullptr, nullptr, nullptr, nullptr, 0);

        cudaMemsetAsync(si, 0, (size_t)128 * N * sizeof(float), 0);
        cudaMemsetAsync(sj, 0, (size_t)128 * N * sizeof(float), 0);

        // edge mm2: xec = KE2 @ relu(norm(t)); xe += 0.1*xec; scatter -> si,sj
        mm_launch(1, E, 128, wE2 + ws, t, 256, E, 128, nullptr, NUL,0,0,0,0, NUL,0,0,0,0,
                  accE, 1.0 / (256.0 * E), nullptr, xe, 2, si, sj, iInd, jInd, N);

        // node mm1: u[256,N] = Wi@si + Wj@sj + Wn@xn   (+stats)
        mm_launch(2, N, 256, wNi + ws, si, 128, N, 256, nullptr,
                  wNj + ws, sj, 128, N, 256,
                  wNn + ws, xn, 128, N, 256,
                  nullptr, 0.0, accN, t, 0, nullptr, nullptr, nullptr, nullptr, 0);

        // node mm2: xn += 0.1 * (KN2 @ relu(norm(u)))
        mm_launch(1, N, 128, wN2 + ws, t, 256, N, 128, nullptr, NUL,0,0,0,0, NUL,0,0,0,0,
                  accN, 1.0 / (256.0 * N), nullptr, xn, 1, nullptr, nullptr, nullptr, nullptr, 0);
    }

    // final: out[64,N] = KNout @ xn   (weights zero-padded to 128 rows; stores guarded by Oact=64)
    mm_launch(1, N, 64, ko, xn, 128, N, 128, nullptr, NUL,0,0,0,0, NUL,0,0,0,0,
              nullptr, 0.0, nullptr, out, 0, nullptr, nullptr, nullptr, nullptr, 0);
}